// round 12
// baseline (speedup 1.0000x reference)
#include <cuda_runtime.h>
#include <cuda_bf16.h>
#include <cuda_fp16.h>
#include <cstdint>

#define N_NODES 100000
#define N_EDGES 3200000
#define TOT_E   (N_EDGES + N_NODES)
#define IN_F    512
#define HID     128
#define TILE_M  128
#define KC      64
#define NCHUNK  (IN_F / KC)     // 8
#define NBLK_SCAN 98

#define A_LD 72                       // elems (64 + 8 pad)
#define W_LD 136                      // elems (128 + 8 pad)
#define ABUF (TILE_M * A_LD)          // 9216 elems
#define WBUF (KC * W_LD)              // 8704 elems
#define BUFE (ABUF + WBUF)            // 17920 elems per buffer
#define S_BYTES (2 * BUFE * 2)        // 71680 bytes

// ---------------- scratch ----------------
__device__ __align__(16) __half g_xh[(size_t)N_NODES * HID];   // fp16 feature cache
__device__ float g_asrc[N_NODES];
__device__ float g_adst[N_NODES];
__device__ int   g_deg[N_NODES];
__device__ int   g_off[N_NODES + 1];
__device__ int   g_cur[N_NODES];
__device__ __align__(16) int2 g_edge[TOT_E];   // (src, exp-bits) sorted by dst
__device__ int   g_is64;
__device__ __align__(16) __half g_wfh[IN_F * HID];   // W fp16 [k][n]
__device__ int   g_part[128];

// ---------------- helpers ----------------
__device__ __forceinline__ uint32_t smem_u32(const void* p) {
    uint32_t a;
    asm("{ .reg .u64 t; cvta.to.shared.u64 t, %1; cvt.u32.u64 %0, t; }" : "=r"(a) : "l"(p));
    return a;
}
__device__ __forceinline__ void ldsm4(uint32_t* r, uint32_t addr) {
    asm volatile("ldmatrix.sync.aligned.m8n8.x4.shared.b16 {%0,%1,%2,%3}, [%4];"
                 : "=r"(r[0]), "=r"(r[1]), "=r"(r[2]), "=r"(r[3]) : "r"(addr));
}
__device__ __forceinline__ void ldsm4t(uint32_t* r, uint32_t addr) {
    asm volatile("ldmatrix.sync.aligned.m8n8.x4.trans.shared.b16 {%0,%1,%2,%3}, [%4];"
                 : "=r"(r[0]), "=r"(r[1]), "=r"(r[2]), "=r"(r[3]) : "r"(addr));
}
__device__ __forceinline__ void mma16816(float* c, const uint32_t* a, const uint32_t* b) {
    asm volatile("mma.sync.aligned.m16n8k16.row.col.f32.f16.f16.f32 "
                 "{%0,%1,%2,%3}, {%4,%5,%6,%7}, {%8,%9}, {%0,%1,%2,%3};"
                 : "+f"(c[0]), "+f"(c[1]), "+f"(c[2]), "+f"(c[3])
                 : "r"(a[0]), "r"(a[1]), "r"(a[2]), "r"(a[3]), "r"(b[0]), "r"(b[1]));
}
__device__ __forceinline__ void cp16(uint32_t dst, const void* src) {
    asm volatile("cp.async.ca.shared.global [%0], [%1], 16;" :: "r"(dst), "l"(src));
}
__device__ __forceinline__ void cp_commit() {
    asm volatile("cp.async.commit_group;" ::: "memory");
}
__device__ __forceinline__ void cp_wait_all() {
    asm volatile("cp.async.wait_group 0;" ::: "memory");
}

// ---------------- adj helpers ----------------
__device__ __forceinline__ int load_adj(const void* adj, long long i, int is64) {
    if (is64) return (int)((const long long*)adj)[i];
    return ((const int*)adj)[i];
}

// ---------------- fused prep: zero degrees + W fp16 + dtype detect ----------------
__global__ void prep_kernel(const void* adj, const float* __restrict__ W) {
    int i = blockIdx.x * blockDim.x + threadIdx.x;
    if (i < N_NODES) g_deg[i] = 0;
    if (i < IN_F * HID) g_wfh[i] = __float2half_rn(W[i]);
    if (i == 0) {
        const int* p = (const int*)adj;
        int acc = 0;
#pragma unroll
        for (int k = 0; k < 64; k++) acc |= p[2 * k + 1];
        for (int k = 0; k < 64; k++) acc |= p[2 * (k * 9973 + 1000) + 1];
        g_is64 = (acc == 0) ? 1 : 0;
    }
}

// ---------------- pipelined fp16 HMMA GEMM + tail histogram, 2 CTAs/SM ----------------
__global__ void __launch_bounds__(256, 2) gemm_kernel(const float* __restrict__ A,
                                                      const float* __restrict__ attsrc,
                                                      const float* __restrict__ attdst,
                                                      const void* __restrict__ adj) {
    extern __shared__ __half sm[];
    const int tid = threadIdx.x, lane = tid & 31, wid = tid >> 5;
    const int row0 = blockIdx.x * TILE_M;
    const int warp_m = wid & 3, warp_n = wid >> 2;

    float acc[16][4];
#pragma unroll
    for (int t = 0; t < 16; t++)
#pragma unroll
        for (int j = 0; j < 4; j++) acc[t][j] = 0.f;

    // A staging: thread -> (row = tid/2, 32-elem half = tid&1)
    const int ar = tid >> 1, ah_ = tid & 1;
    const int agr = row0 + ar;
    // W cp.async: 1024 16B-chunks per K-chunk; 4 per thread
    const int wc0 = (tid & 15) * 8;

    uint32_t h[16];

#define LOAD_A(c) do {                                                          \
        const int k0 = (c) * KC;                                                \
        if (agr < N_NODES) {                                                    \
            const float4* src = (const float4*)&A[(size_t)agr * IN_F + k0 + ah_ * 32]; \
            _Pragma("unroll")                                                   \
            for (int q = 0; q < 8; q++) {                                       \
                float4 v = src[q];                                              \
                __half2 p0 = __floats2half2_rn(v.x, v.y);                       \
                __half2 p1 = __floats2half2_rn(v.z, v.w);                       \
                h[2*q]   = *reinterpret_cast<uint32_t*>(&p0);                   \
                h[2*q+1] = *reinterpret_cast<uint32_t*>(&p1);                   \
            }                                                                   \
        } else {                                                                \
            _Pragma("unroll")                                                   \
            for (int q = 0; q < 16; q++) h[q] = 0u;                             \
        }                                                                       \
    } while (0)

#define STORE_A(b) do {                                                         \
        __half* ph = &(sm + (b) * BUFE)[ar * A_LD + ah_ * 32];                  \
        *(uint4*)(ph)      = make_uint4(h[0],  h[1],  h[2],  h[3]);             \
        *(uint4*)(ph + 8)  = make_uint4(h[4],  h[5],  h[6],  h[7]);             \
        *(uint4*)(ph + 16) = make_uint4(h[8],  h[9],  h[10], h[11]);            \
        *(uint4*)(ph + 24) = make_uint4(h[12], h[13], h[14], h[15]);            \
    } while (0)

#define ISSUE_W(c, b) do {                                                      \
        const int k0 = (c) * KC;                                                \
        uint32_t wh = smem_u32(sm + (b) * BUFE + ABUF);                         \
        _Pragma("unroll")                                                       \
        for (int j = 0; j < 4; j++) {                                           \
            int wrow = (tid + 256 * j) >> 4;                                    \
            cp16(wh + (wrow * W_LD + wc0) * 2,                                  \
                 &g_wfh[(size_t)(k0 + wrow) * HID + wc0]);                      \
        }                                                                       \
        cp_commit();                                                            \
    } while (0)

    ISSUE_W(0, 0);
    LOAD_A(0);
    STORE_A(0);
    cp_wait_all();
    __syncthreads();

    for (int c = 0; c < NCHUNK; c++) {
        const int buf = c & 1;
        if (c < NCHUNK - 1) {
            ISSUE_W(c + 1, buf ^ 1);
            LOAD_A(c + 1);          // LDGs + converts overlap the MMAs below
        }

        const __half* Ah = sm + buf * BUFE;
        const __half* Wh = Ah + ABUF;

#pragma unroll
        for (int ks = 0; ks < 4; ks++) {
            uint32_t a_h[2][4];
#pragma unroll
            for (int mi = 0; mi < 2; mi++) {
                uint32_t aoff = (warp_m * 32 + mi * 16 + (lane & 15)) * A_LD
                              + ks * 16 + (lane >> 4) * 8;
                ldsm4(a_h[mi], smem_u32(&Ah[aoff]));
            }
#pragma unroll
            for (int nt = 0; nt < 4; nt++) {
                uint32_t b_h[4];
                uint32_t woff = (ks * 16 + (lane & 15)) * W_LD
                              + warp_n * 64 + nt * 16 + (lane >> 4) * 8;
                ldsm4t(b_h, smem_u32(&Wh[woff]));
#pragma unroll
                for (int mi = 0; mi < 2; mi++) {
                    int t = mi * 8 + nt * 2;
                    mma16816(acc[t],     a_h[mi], b_h);
                    mma16816(acc[t + 1], a_h[mi], b_h + 2);
                }
            }
        }
        if (c < NCHUNK - 1) {
            STORE_A(buf ^ 1);
            cp_wait_all();
        }
        __syncthreads();
    }

    // ---- epilogue: fp16 g_xh + fused attention dots ----
    float sd[2][2] = {{0.f, 0.f}, {0.f, 0.f}};
    float dd[2][2] = {{0.f, 0.f}, {0.f, 0.f}};
#pragma unroll
    for (int mi = 0; mi < 2; mi++) {
        const int rlo = row0 + warp_m * 32 + mi * 16 + (lane >> 2);
        const int rhi = rlo + 8;
#pragma unroll
        for (int nt = 0; nt < 4; nt++) {
#pragma unroll
            for (int hh = 0; hh < 2; hh++) {
                int t = mi * 8 + nt * 2 + hh;
                int col = warp_n * 64 + nt * 16 + hh * 8 + (lane & 3) * 2;
                float as0 = __ldg(&attsrc[col]), as1 = __ldg(&attsrc[col + 1]);
                float ad0 = __ldg(&attdst[col]), ad1 = __ldg(&attdst[col + 1]);
                float2 v0 = make_float2(acc[t][0], acc[t][1]);
                float2 v1 = make_float2(acc[t][2], acc[t][3]);
                sd[mi][0] += v0.x * as0 + v0.y * as1;
                dd[mi][0] += v0.x * ad0 + v0.y * ad1;
                sd[mi][1] += v1.x * as0 + v1.y * as1;
                dd[mi][1] += v1.x * ad0 + v1.y * ad1;
                if (rlo < N_NODES) {
                    __half2 p = __float22half2_rn(v0);
                    *(uint32_t*)&g_xh[(size_t)rlo * HID + col] = *(uint32_t*)&p;
                }
                if (rhi < N_NODES) {
                    __half2 p = __float22half2_rn(v1);
                    *(uint32_t*)&g_xh[(size_t)rhi * HID + col] = *(uint32_t*)&p;
                }
            }
        }
    }
#pragma unroll
    for (int o = 1; o <= 2; o <<= 1) {
#pragma unroll
        for (int mi = 0; mi < 2; mi++)
#pragma unroll
            for (int hh = 0; hh < 2; hh++) {
                sd[mi][hh] += __shfl_xor_sync(0xffffffffu, sd[mi][hh], o);
                dd[mi][hh] += __shfl_xor_sync(0xffffffffu, dd[mi][hh], o);
            }
    }
    float* sdp = (float*)sm;
    float* ddp = sdp + 256;
    if ((lane & 3) == 0) {
#pragma unroll
        for (int mi = 0; mi < 2; mi++)
#pragma unroll
            for (int hh = 0; hh < 2; hh++) {
                int rt = warp_m * 32 + mi * 16 + (lane >> 2) + hh * 8;
                sdp[rt * 2 + warp_n] = sd[mi][hh];
                ddp[rt * 2 + warp_n] = dd[mi][hh];
            }
    }
    __syncthreads();
    if (tid < 128) {
        int gr = row0 + tid;
        if (gr < N_NODES) {
            g_asrc[gr] = sdp[tid * 2] + sdp[tid * 2 + 1];
            g_adst[gr] = ddp[tid * 2] + ddp[tid * 2 + 1];
        }
    }

    // ---- tail histogram: overlaps other CTAs' mainloops; atomics drain async ----
    {
        const int is64 = g_is64;
        const int gsz = gridDim.x * blockDim.x;
        for (int i = blockIdx.x * blockDim.x + tid; i < TOT_E; i += gsz) {
            int d = (i < N_EDGES) ? load_adj(adj, (long long)N_EDGES + i, is64)
                                  : (i - N_EDGES);
            atomicAdd(&g_deg[d], 1);
        }
    }
}

// ---------------- device-wide scan ----------------
__global__ void __launch_bounds__(1024) scan1_kernel() {
    __shared__ int ws[32];
    int tid = threadIdx.x, lane = tid & 31, wid = tid >> 5;
    int i = blockIdx.x * 1024 + tid;
    int v = (i < N_NODES) ? g_deg[i] : 0;
#pragma unroll
    for (int o = 16; o; o >>= 1) v += __shfl_down_sync(0xffffffffu, v, o);
    if (lane == 0) ws[wid] = v;
    __syncthreads();
    if (wid == 0) {
        int s = ws[lane];
#pragma unroll
        for (int o = 16; o; o >>= 1) s += __shfl_down_sync(0xffffffffu, s, o);
        if (lane == 0) g_part[blockIdx.x] = s;
    }
}
__global__ void scan2_kernel() {
    __shared__ int ws[4];
    int tid = threadIdx.x, lane = tid & 31, wid = tid >> 5;
    int v = (tid < NBLK_SCAN) ? g_part[tid] : 0;
    int incl = v;
#pragma unroll
    for (int o = 1; o < 32; o <<= 1) {
        int t = __shfl_up_sync(0xffffffffu, incl, o);
        if (lane >= o) incl += t;
    }
    if (lane == 31) ws[wid] = incl;
    __syncthreads();
    int base = 0;
    for (int w = 0; w < wid; w++) base += ws[w];
    if (tid < NBLK_SCAN) g_part[tid] = base + incl - v;
    if (tid == 127) g_off[N_NODES] = base + incl;
}
__global__ void __launch_bounds__(1024) scan3_kernel() {
    __shared__ int ws[32];
    int tid = threadIdx.x, lane = tid & 31, wid = tid >> 5;
    int i = blockIdx.x * 1024 + tid;
    int v = (i < N_NODES) ? g_deg[i] : 0;
    int incl = v;
#pragma unroll
    for (int o = 1; o < 32; o <<= 1) {
        int t = __shfl_up_sync(0xffffffffu, incl, o);
        if (lane >= o) incl += t;
    }
    if (lane == 31) ws[wid] = incl;
    __syncthreads();
    if (wid == 0) {
        int s = ws[lane];
        int sc = s;
#pragma unroll
        for (int o = 1; o < 32; o <<= 1) {
            int t = __shfl_up_sync(0xffffffffu, sc, o);
            if (lane >= o) sc += t;
        }
        ws[lane] = sc - s;
    }
    __syncthreads();
    int excl = g_part[blockIdx.x] + ws[wid] + incl - v;
    if (i < N_NODES) { g_off[i] = excl; g_cur[i] = excl; }
}

// ---------------- scatter (packed int2 writes) ----------------
__global__ void scatter_kernel(const void* __restrict__ adj) {
    int i = blockIdx.x * blockDim.x + threadIdx.x;
    if (i >= TOT_E) return;
    int is64 = g_is64;
    int s, d;
    if (i < N_EDGES) {
        s = load_adj(adj, i, is64);
        d = load_adj(adj, (long long)N_EDGES + i, is64);
    } else {
        s = i - N_EDGES;
        d = s;
    }
    float e = g_asrc[s] + g_adst[d];
    e = (e > 0.f) ? e : 0.2f * e;
    float ex = __expf(e);
    int pos = atomicAdd(&g_cur[d], 1);
    g_edge[pos] = make_int2(s, __float_as_int(ex));
}

// ---------------- aggregation (fp16 gather, unroll-2) ----------------
__global__ void agg_kernel(const float* __restrict__ bias, float* __restrict__ out) {
    int w = (blockIdx.x * blockDim.x + threadIdx.x) >> 5;
    int lane = threadIdx.x & 31;
    if (w >= N_NODES) return;
    int st = g_off[w], en = g_off[w + 1];
    float4 acc = make_float4(0.f, 0.f, 0.f, 0.f);
    float ssum = 0.f;
    int j = st;
    for (; j + 1 < en; j += 2) {
        int2 se0 = g_edge[j];
        int2 se1 = g_edge[j + 1];
        float ex0 = __int_as_float(se0.y);
        float ex1 = __int_as_float(se1.y);
        uint2 raw0 = *(const uint2*)&g_xh[(size_t)se0.x * HID + lane * 4];
        uint2 raw1 = *(const uint2*)&g_xh[(size_t)se1.x * HID + lane * 4];
        float2 a0 = __half22float2(*reinterpret_cast<__half2*>(&raw0.x));
        float2 a1 = __half22float2(*reinterpret_cast<__half2*>(&raw0.y));
        float2 b0 = __half22float2(*reinterpret_cast<__half2*>(&raw1.x));
        float2 b1 = __half22float2(*reinterpret_cast<__half2*>(&raw1.y));
        ssum += ex0 + ex1;
        acc.x += ex0 * a0.x + ex1 * b0.x;
        acc.y += ex0 * a0.y + ex1 * b0.y;
        acc.z += ex0 * a1.x + ex1 * b1.x;
        acc.w += ex0 * a1.y + ex1 * b1.y;
    }
    if (j < en) {
        int2 se = g_edge[j];
        float ex = __int_as_float(se.y);
        uint2 raw = *(const uint2*)&g_xh[(size_t)se.x * HID + lane * 4];
        float2 f0 = __half22float2(*reinterpret_cast<__half2*>(&raw.x));
        float2 f1 = __half22float2(*reinterpret_cast<__half2*>(&raw.y));
        ssum += ex;
        acc.x += ex * f0.x;
        acc.y += ex * f0.y;
        acc.z += ex * f1.x;
        acc.w += ex * f1.y;
    }
    float inv = 1.f / (ssum + 1e-16f);
    float4 b = *(const float4*)&bias[lane * 4];
    float4 o;
    o.x = acc.x * inv + b.x;
    o.y = acc.y * inv + b.y;
    o.z = acc.z * inv + b.z;
    o.w = acc.w * inv + b.w;
    o.x = (o.x > 0.f) ? o.x : 0.25f * o.x;
    o.y = (o.y > 0.f) ? o.y : 0.25f * o.y;
    o.z = (o.z > 0.f) ? o.z : 0.25f * o.z;
    o.w = (o.w > 0.f) ? o.w : 0.25f * o.w;
    *(float4*)&out[(size_t)w * HID + lane * 4] = o;
}

// ---------------- launcher ----------------
extern "C" void kernel_launch(void* const* d_in, const int* in_sizes, int n_in,
                              void* d_out, int out_size) {
    const float* data   = (const float*)d_in[0];
    const void*  adj    = (const void*)d_in[1];
    const float* W      = (const float*)d_in[2];
    const float* attsrc = (const float*)d_in[3];
    const float* attdst = (const float*)d_in[4];
    const float* bias   = (const float*)d_in[5];
    float* out = (float*)d_out;

    cudaFuncSetAttribute(gemm_kernel, cudaFuncAttributeMaxDynamicSharedMemorySize, S_BYTES);

    prep_kernel<<<(N_NODES + 255) / 256, 256>>>(adj, W);
    gemm_kernel<<<(N_NODES + TILE_M - 1) / TILE_M, 256, S_BYTES>>>(data, attsrc, attdst, adj);
    scan1_kernel<<<NBLK_SCAN, 1024>>>();
    scan2_kernel<<<1, 128>>>();
    scan3_kernel<<<NBLK_SCAN, 1024>>>();
    scatter_kernel<<<(TOT_E + 255) / 256, 256>>>(adj);
    agg_kernel<<<(N_NODES * 32 + 255) / 256, 256>>>(bias, out);
}

// round 13
// speedup vs baseline: 1.0623x; 1.0623x over previous
#include <cuda_runtime.h>
#include <cuda_bf16.h>
#include <cuda_fp16.h>
#include <cstdint>

#define N_NODES 100000
#define N_EDGES 3200000
#define IN_F    512
#define HID     128
#define TILE_M  128
#define KC      64
#define NCHUNK  (IN_F / KC)     // 8
#define NBLK_SCAN 98

#define A_LD 72                       // elems (64 + 8 pad)
#define W_LD 136                      // elems (128 + 8 pad)
#define ABUF (TILE_M * A_LD)          // 9216 elems
#define WBUF (KC * W_LD)              // 8704 elems
#define BUFE (ABUF + WBUF)            // 17920 elems per buffer
#define S_BYTES (2 * BUFE * 2)        // 71680 bytes

// ---------------- scratch ----------------
__device__ __align__(16) __half g_xh[(size_t)N_NODES * HID];   // fp16 feature cache
__device__ float g_asrc[N_NODES];
__device__ float g_adst[N_NODES];
__device__ int   g_deg[N_NODES];
__device__ int   g_off[N_NODES + 1];
__device__ int   g_cur[N_NODES];
__device__ __align__(16) int2 g_edge[N_EDGES];   // (src, exp-bits) sorted by dst
__device__ int   g_is64;
__device__ __align__(16) __half g_wfh[IN_F * HID];   // W fp16 [k][n]
__device__ int   g_part[128];

// ---------------- helpers ----------------
__device__ __forceinline__ uint32_t smem_u32(const void* p) {
    uint32_t a;
    asm("{ .reg .u64 t; cvta.to.shared.u64 t, %1; cvt.u32.u64 %0, t; }" : "=r"(a) : "l"(p));
    return a;
}
__device__ __forceinline__ void ldsm4(uint32_t* r, uint32_t addr) {
    asm volatile("ldmatrix.sync.aligned.m8n8.x4.shared.b16 {%0,%1,%2,%3}, [%4];"
                 : "=r"(r[0]), "=r"(r[1]), "=r"(r[2]), "=r"(r[3]) : "r"(addr));
}
__device__ __forceinline__ void ldsm4t(uint32_t* r, uint32_t addr) {
    asm volatile("ldmatrix.sync.aligned.m8n8.x4.trans.shared.b16 {%0,%1,%2,%3}, [%4];"
                 : "=r"(r[0]), "=r"(r[1]), "=r"(r[2]), "=r"(r[3]) : "r"(addr));
}
__device__ __forceinline__ void mma16816(float* c, const uint32_t* a, const uint32_t* b) {
    asm volatile("mma.sync.aligned.m16n8k16.row.col.f32.f16.f16.f32 "
                 "{%0,%1,%2,%3}, {%4,%5,%6,%7}, {%8,%9}, {%0,%1,%2,%3};"
                 : "+f"(c[0]), "+f"(c[1]), "+f"(c[2]), "+f"(c[3])
                 : "r"(a[0]), "r"(a[1]), "r"(a[2]), "r"(a[3]), "r"(b[0]), "r"(b[1]));
}
__device__ __forceinline__ void cp16(uint32_t dst, const void* src) {
    asm volatile("cp.async.ca.shared.global [%0], [%1], 16;" :: "r"(dst), "l"(src));
}
__device__ __forceinline__ void cp_commit() {
    asm volatile("cp.async.commit_group;" ::: "memory");
}
__device__ __forceinline__ void cp_wait_all() {
    asm volatile("cp.async.wait_group 0;" ::: "memory");
}

// ---------------- adj helpers ----------------
__device__ __forceinline__ int load_adj(const void* adj, long long i, int is64) {
    if (is64) return (int)((const long long*)adj)[i];
    return ((const int*)adj)[i];
}

// ---------------- fused prep: zero degrees + W fp16 + dtype detect ----------------
__global__ void prep_kernel(const void* adj, const float* __restrict__ W) {
    int i = blockIdx.x * blockDim.x + threadIdx.x;
    if (i < N_NODES) g_deg[i] = 0;
    if (i < IN_F * HID) g_wfh[i] = __float2half_rn(W[i]);
    if (i == 0) {
        const int* p = (const int*)adj;
        int acc = 0;
#pragma unroll
        for (int k = 0; k < 64; k++) acc |= p[2 * k + 1];
        for (int k = 0; k < 64; k++) acc |= p[2 * (k * 9973 + 1000) + 1];
        g_is64 = (acc == 0) ? 1 : 0;
    }
}

// ---------------- pipelined fp16 HMMA GEMM, 2 CTAs/SM ----------------
__global__ void __launch_bounds__(256, 2) gemm_kernel(const float* __restrict__ A,
                                                      const float* __restrict__ attsrc,
                                                      const float* __restrict__ attdst) {
    extern __shared__ __half sm[];
    const int tid = threadIdx.x, lane = tid & 31, wid = tid >> 5;
    const int row0 = blockIdx.x * TILE_M;
    const int warp_m = wid & 3, warp_n = wid >> 2;

    float acc[16][4];
#pragma unroll
    for (int t = 0; t < 16; t++)
#pragma unroll
        for (int j = 0; j < 4; j++) acc[t][j] = 0.f;

    const int ar = tid >> 1, ah_ = tid & 1;
    const int agr = row0 + ar;
    const int wc0 = (tid & 15) * 8;

    uint32_t h[16];

#define LOAD_A(c) do {                                                          \
        const int k0 = (c) * KC;                                                \
        if (agr < N_NODES) {                                                    \
            const float4* src = (const float4*)&A[(size_t)agr * IN_F + k0 + ah_ * 32]; \
            _Pragma("unroll")                                                   \
            for (int q = 0; q < 8; q++) {                                       \
                float4 v = src[q];                                              \
                __half2 p0 = __floats2half2_rn(v.x, v.y);                       \
                __half2 p1 = __floats2half2_rn(v.z, v.w);                       \
                h[2*q]   = *reinterpret_cast<uint32_t*>(&p0);                   \
                h[2*q+1] = *reinterpret_cast<uint32_t*>(&p1);                   \
            }                                                                   \
        } else {                                                                \
            _Pragma("unroll")                                                   \
            for (int q = 0; q < 16; q++) h[q] = 0u;                             \
        }                                                                       \
    } while (0)

#define STORE_A(b) do {                                                         \
        __half* ph = &(sm + (b) * BUFE)[ar * A_LD + ah_ * 32];                  \
        *(uint4*)(ph)      = make_uint4(h[0],  h[1],  h[2],  h[3]);             \
        *(uint4*)(ph + 8)  = make_uint4(h[4],  h[5],  h[6],  h[7]);             \
        *(uint4*)(ph + 16) = make_uint4(h[8],  h[9],  h[10], h[11]);            \
        *(uint4*)(ph + 24) = make_uint4(h[12], h[13], h[14], h[15]);            \
    } while (0)

#define ISSUE_W(c, b) do {                                                      \
        const int k0 = (c) * KC;                                                \
        uint32_t wh = smem_u32(sm + (b) * BUFE + ABUF);                         \
        _Pragma("unroll")                                                       \
        for (int j = 0; j < 4; j++) {                                           \
            int wrow = (tid + 256 * j) >> 4;                                    \
            cp16(wh + (wrow * W_LD + wc0) * 2,                                  \
                 &g_wfh[(size_t)(k0 + wrow) * HID + wc0]);                      \
        }                                                                       \
        cp_commit();                                                            \
    } while (0)

    ISSUE_W(0, 0);
    LOAD_A(0);
    STORE_A(0);
    cp_wait_all();
    __syncthreads();

    for (int c = 0; c < NCHUNK; c++) {
        const int buf = c & 1;
        if (c < NCHUNK - 1) {
            ISSUE_W(c + 1, buf ^ 1);
            LOAD_A(c + 1);
        }

        const __half* Ah = sm + buf * BUFE;
        const __half* Wh = Ah + ABUF;

#pragma unroll
        for (int ks = 0; ks < 4; ks++) {
            uint32_t a_h[2][4];
#pragma unroll
            for (int mi = 0; mi < 2; mi++) {
                uint32_t aoff = (warp_m * 32 + mi * 16 + (lane & 15)) * A_LD
                              + ks * 16 + (lane >> 4) * 8;
                ldsm4(a_h[mi], smem_u32(&Ah[aoff]));
            }
#pragma unroll
            for (int nt = 0; nt < 4; nt++) {
                uint32_t b_h[4];
                uint32_t woff = (ks * 16 + (lane & 15)) * W_LD
                              + warp_n * 64 + nt * 16 + (lane >> 4) * 8;
                ldsm4t(b_h, smem_u32(&Wh[woff]));
#pragma unroll
                for (int mi = 0; mi < 2; mi++) {
                    int t = mi * 8 + nt * 2;
                    mma16816(acc[t],     a_h[mi], b_h);
                    mma16816(acc[t + 1], a_h[mi], b_h + 2);
                }
            }
        }
        if (c < NCHUNK - 1) {
            STORE_A(buf ^ 1);
            cp_wait_all();
        }
        __syncthreads();
    }

    // ---- epilogue: fp16 g_xh + fused attention dots ----
    float sd[2][2] = {{0.f, 0.f}, {0.f, 0.f}};
    float dd[2][2] = {{0.f, 0.f}, {0.f, 0.f}};
#pragma unroll
    for (int mi = 0; mi < 2; mi++) {
        const int rlo = row0 + warp_m * 32 + mi * 16 + (lane >> 2);
        const int rhi = rlo + 8;
#pragma unroll
        for (int nt = 0; nt < 4; nt++) {
#pragma unroll
            for (int hh = 0; hh < 2; hh++) {
                int t = mi * 8 + nt * 2 + hh;
                int col = warp_n * 64 + nt * 16 + hh * 8 + (lane & 3) * 2;
                float as0 = __ldg(&attsrc[col]), as1 = __ldg(&attsrc[col + 1]);
                float ad0 = __ldg(&attdst[col]), ad1 = __ldg(&attdst[col + 1]);
                float2 v0 = make_float2(acc[t][0], acc[t][1]);
                float2 v1 = make_float2(acc[t][2], acc[t][3]);
                sd[mi][0] += v0.x * as0 + v0.y * as1;
                dd[mi][0] += v0.x * ad0 + v0.y * ad1;
                sd[mi][1] += v1.x * as0 + v1.y * as1;
                dd[mi][1] += v1.x * ad0 + v1.y * ad1;
                if (rlo < N_NODES) {
                    __half2 p = __float22half2_rn(v0);
                    *(uint32_t*)&g_xh[(size_t)rlo * HID + col] = *(uint32_t*)&p;
                }
                if (rhi < N_NODES) {
                    __half2 p = __float22half2_rn(v1);
                    *(uint32_t*)&g_xh[(size_t)rhi * HID + col] = *(uint32_t*)&p;
                }
            }
        }
    }
#pragma unroll
    for (int o = 1; o <= 2; o <<= 1) {
#pragma unroll
        for (int mi = 0; mi < 2; mi++)
#pragma unroll
            for (int hh = 0; hh < 2; hh++) {
                sd[mi][hh] += __shfl_xor_sync(0xffffffffu, sd[mi][hh], o);
                dd[mi][hh] += __shfl_xor_sync(0xffffffffu, dd[mi][hh], o);
            }
    }
    float* sdp = (float*)sm;
    float* ddp = sdp + 256;
    if ((lane & 3) == 0) {
#pragma unroll
        for (int mi = 0; mi < 2; mi++)
#pragma unroll
            for (int hh = 0; hh < 2; hh++) {
                int rt = warp_m * 32 + mi * 16 + (lane >> 2) + hh * 8;
                sdp[rt * 2 + warp_n] = sd[mi][hh];
                ddp[rt * 2 + warp_n] = dd[mi][hh];
            }
    }
    __syncthreads();
    if (tid < 128) {
        int gr = row0 + tid;
        if (gr < N_NODES) {
            g_asrc[gr] = sdp[tid * 2] + sdp[tid * 2 + 1];
            g_adst[gr] = ddp[tid * 2] + ddp[tid * 2 + 1];
        }
    }
}

// ---------------- histogram (real edges only; self-loops analytic) ----------------
__global__ void hist_kernel(const void* __restrict__ adj) {
    int i = blockIdx.x * blockDim.x + threadIdx.x;
    if (i >= N_EDGES) return;
    int is64 = g_is64;
    int d = load_adj(adj, (long long)N_EDGES + i, is64);
    atomicAdd(&g_deg[d], 1);
}

// ---------------- scan: per-block sums, then fused base+scan ----------------
__global__ void __launch_bounds__(1024) scan1_kernel() {
    __shared__ int ws[32];
    int tid = threadIdx.x, lane = tid & 31, wid = tid >> 5;
    int i = blockIdx.x * 1024 + tid;
    int v = (i < N_NODES) ? g_deg[i] : 0;
#pragma unroll
    for (int o = 16; o; o >>= 1) v += __shfl_down_sync(0xffffffffu, v, o);
    if (lane == 0) ws[wid] = v;
    __syncthreads();
    if (wid == 0) {
        int s = ws[lane];
#pragma unroll
        for (int o = 16; o; o >>= 1) s += __shfl_down_sync(0xffffffffu, s, o);
        if (lane == 0) g_part[blockIdx.x] = s;
    }
}
__global__ void __launch_bounds__(1024) scan2_kernel() {
    __shared__ int ws[32];
    __shared__ int s_base;
    int tid = threadIdx.x, lane = tid & 31, wid = tid >> 5;
    // block base = sum of g_part[j < blockIdx.x]
    {
        int p = (tid < blockIdx.x) ? g_part[tid] : 0;   // blockIdx.x <= 97 < 1024
#pragma unroll
        for (int o = 16; o; o >>= 1) p += __shfl_down_sync(0xffffffffu, p, o);
        if (lane == 0) ws[wid] = p;
        __syncthreads();
        if (wid == 0) {
            int s = ws[lane];
#pragma unroll
            for (int o = 16; o; o >>= 1) s += __shfl_down_sync(0xffffffffu, s, o);
            if (lane == 0) s_base = s;
        }
        __syncthreads();
    }
    int i = blockIdx.x * 1024 + tid;
    int v = (i < N_NODES) ? g_deg[i] : 0;
    int incl = v;
#pragma unroll
    for (int o = 1; o < 32; o <<= 1) {
        int t = __shfl_up_sync(0xffffffffu, incl, o);
        if (lane >= o) incl += t;
    }
    __syncthreads();
    if (lane == 31) ws[wid] = incl;
    __syncthreads();
    if (wid == 0) {
        int s = ws[lane];
        int sc = s;
#pragma unroll
        for (int o = 1; o < 32; o <<= 1) {
            int t = __shfl_up_sync(0xffffffffu, sc, o);
            if (lane >= o) sc += t;
        }
        ws[lane] = sc - s;
    }
    __syncthreads();
    int excl = s_base + ws[wid] + incl - v;
    if (i < N_NODES) {
        g_off[i] = excl;
        g_cur[i] = excl;
        if (i == N_NODES - 1) g_off[N_NODES] = excl + v;
    }
}

// ---------------- scatter (real edges only) ----------------
__global__ void scatter_kernel(const void* __restrict__ adj) {
    int i = blockIdx.x * blockDim.x + threadIdx.x;
    if (i >= N_EDGES) return;
    int is64 = g_is64;
    int s = load_adj(adj, i, is64);
    int d = load_adj(adj, (long long)N_EDGES + i, is64);
    float e = g_asrc[s] + g_adst[d];
    e = (e > 0.f) ? e : 0.2f * e;
    float ex = __expf(e);
    int pos = atomicAdd(&g_cur[d], 1);
    g_edge[pos] = make_int2(s, __float_as_int(ex));
}

// ---------------- aggregation (fp16 gather; self-loop analytic) ----------------
__global__ void agg_kernel(const float* __restrict__ bias, float* __restrict__ out) {
    int w = (blockIdx.x * blockDim.x + threadIdx.x) >> 5;
    int lane = threadIdx.x & 31;
    if (w >= N_NODES) return;
    int st = g_off[w], en = g_off[w + 1];
    // self-loop term
    float es = g_asrc[w] + g_adst[w];
    es = (es > 0.f) ? es : 0.2f * es;
    float ssum = __expf(es);
    float4 acc;
    {
        uint2 raw = *(const uint2*)&g_xh[(size_t)w * HID + lane * 4];
        float2 f0 = __half22float2(*reinterpret_cast<__half2*>(&raw.x));
        float2 f1 = __half22float2(*reinterpret_cast<__half2*>(&raw.y));
        acc = make_float4(ssum * f0.x, ssum * f0.y, ssum * f1.x, ssum * f1.y);
    }
    for (int j = st; j < en; j++) {
        int2 se = g_edge[j];
        float ex = __int_as_float(se.y);
        uint2 raw = *(const uint2*)&g_xh[(size_t)se.x * HID + lane * 4];
        float2 f0 = __half22float2(*reinterpret_cast<__half2*>(&raw.x));
        float2 f1 = __half22float2(*reinterpret_cast<__half2*>(&raw.y));
        ssum += ex;
        acc.x += ex * f0.x;
        acc.y += ex * f0.y;
        acc.z += ex * f1.x;
        acc.w += ex * f1.y;
    }
    float inv = 1.f / (ssum + 1e-16f);
    float4 b = *(const float4*)&bias[lane * 4];
    float4 o;
    o.x = acc.x * inv + b.x;
    o.y = acc.y * inv + b.y;
    o.z = acc.z * inv + b.z;
    o.w = acc.w * inv + b.w;
    o.x = (o.x > 0.f) ? o.x : 0.25f * o.x;
    o.y = (o.y > 0.f) ? o.y : 0.25f * o.y;
    o.z = (o.z > 0.f) ? o.z : 0.25f * o.z;
    o.w = (o.w > 0.f) ? o.w : 0.25f * o.w;
    *(float4*)&out[(size_t)w * HID + lane * 4] = o;
}

// ---------------- launcher ----------------
extern "C" void kernel_launch(void* const* d_in, const int* in_sizes, int n_in,
                              void* d_out, int out_size) {
    const float* data   = (const float*)d_in[0];
    const void*  adj    = (const void*)d_in[1];
    const float* W      = (const float*)d_in[2];
    const float* attsrc = (const float*)d_in[3];
    const float* attdst = (const float*)d_in[4];
    const float* bias   = (const float*)d_in[5];
    float* out = (float*)d_out;

    cudaFuncSetAttribute(gemm_kernel, cudaFuncAttributeMaxDynamicSharedMemorySize, S_BYTES);

    prep_kernel<<<(N_NODES + 255) / 256, 256>>>(adj, W);
    gemm_kernel<<<(N_NODES + TILE_M - 1) / TILE_M, 256, S_BYTES>>>(data, attsrc, attdst);
    hist_kernel<<<(N_EDGES + 255) / 256, 256>>>(adj);
    scan1_kernel<<<NBLK_SCAN, 1024>>>();
    scan2_kernel<<<NBLK_SCAN, 1024>>>();
    scatter_kernel<<<(N_EDGES + 255) / 256, 256>>>(adj);
    agg_kernel<<<(N_NODES * 32 + 255) / 256, 256>>>(bias, out);
}

// round 14
// speedup vs baseline: 1.0626x; 1.0002x over previous
#include <cuda_runtime.h>
#include <cuda_bf16.h>
#include <cuda_fp16.h>
#include <cstdint>

#define N_NODES 100000
#define N_EDGES 3200000
#define IN_F    512
#define HID     128
#define TILE_M  128
#define KC      64
#define NCHUNK  (IN_F / KC)     // 8
#define NBLK_SCAN 98

#define A_LD 72                       // elems (64 + 8 pad)
#define W_LD 136                      // elems (128 + 8 pad)
#define ABUF (TILE_M * A_LD)          // 9216 elems
#define WBUF (KC * W_LD)              // 8704 elems
#define BUFE (ABUF + WBUF)            // 17920 elems per buffer
#define S_BYTES (2 * BUFE * 2)        // 71680 bytes

// ---------------- scratch ----------------
__device__ __align__(16) __half g_xh[(size_t)N_NODES * HID];   // fp16 feature cache
__device__ float g_asrc[N_NODES];
__device__ float g_adst[N_NODES];
__device__ int   g_deg[N_NODES];
__device__ int   g_off[N_NODES + 1];
__device__ int   g_cur[N_NODES];
__device__ __align__(16) int2 g_edge[N_EDGES];   // (src, exp-bits) sorted by dst
__device__ int   g_is64;
__device__ __align__(16) __half g_wfh[IN_F * HID];   // W fp16 [k][n]
__device__ int   g_part[128];

// ---------------- helpers ----------------
__device__ __forceinline__ uint32_t smem_u32(const void* p) {
    uint32_t a;
    asm("{ .reg .u64 t; cvta.to.shared.u64 t, %1; cvt.u32.u64 %0, t; }" : "=r"(a) : "l"(p));
    return a;
}
__device__ __forceinline__ void ldsm4(uint32_t* r, uint32_t addr) {
    asm volatile("ldmatrix.sync.aligned.m8n8.x4.shared.b16 {%0,%1,%2,%3}, [%4];"
                 : "=r"(r[0]), "=r"(r[1]), "=r"(r[2]), "=r"(r[3]) : "r"(addr));
}
__device__ __forceinline__ void ldsm4t(uint32_t* r, uint32_t addr) {
    asm volatile("ldmatrix.sync.aligned.m8n8.x4.trans.shared.b16 {%0,%1,%2,%3}, [%4];"
                 : "=r"(r[0]), "=r"(r[1]), "=r"(r[2]), "=r"(r[3]) : "r"(addr));
}
__device__ __forceinline__ void mma16816(float* c, const uint32_t* a, const uint32_t* b) {
    asm volatile("mma.sync.aligned.m16n8k16.row.col.f32.f16.f16.f32 "
                 "{%0,%1,%2,%3}, {%4,%5,%6,%7}, {%8,%9}, {%0,%1,%2,%3};"
                 : "+f"(c[0]), "+f"(c[1]), "+f"(c[2]), "+f"(c[3])
                 : "r"(a[0]), "r"(a[1]), "r"(a[2]), "r"(a[3]), "r"(b[0]), "r"(b[1]));
}
__device__ __forceinline__ void cp16(uint32_t dst, const void* src) {
    asm volatile("cp.async.ca.shared.global [%0], [%1], 16;" :: "r"(dst), "l"(src));
}
__device__ __forceinline__ void cp_commit() {
    asm volatile("cp.async.commit_group;" ::: "memory");
}
__device__ __forceinline__ void cp_wait_all() {
    asm volatile("cp.async.wait_group 0;" ::: "memory");
}

// ---------------- adj helpers ----------------
__device__ __forceinline__ int load_adj(const void* adj, long long i, int is64) {
    if (is64) return (int)((const long long*)adj)[i];
    return ((const int*)adj)[i];
}

// ---------------- fused prep: zero degrees + W fp16 + dtype detect ----------------
__global__ void prep_kernel(const void* adj, const float* __restrict__ W) {
    int i = blockIdx.x * blockDim.x + threadIdx.x;
    if (i < N_NODES) g_deg[i] = 0;
    if (i < IN_F * HID) g_wfh[i] = __float2half_rn(W[i]);
    if (i == 0) {
        const int* p = (const int*)adj;
        int acc = 0;
#pragma unroll
        for (int k = 0; k < 64; k++) acc |= p[2 * k + 1];
        for (int k = 0; k < 64; k++) acc |= p[2 * (k * 9973 + 1000) + 1];
        g_is64 = (acc == 0) ? 1 : 0;
    }
}

// ---------------- pipelined fp16 HMMA GEMM, 2 CTAs/SM ----------------
__global__ void __launch_bounds__(256, 2) gemm_kernel(const float* __restrict__ A,
                                                      const float* __restrict__ attsrc,
                                                      const float* __restrict__ attdst) {
    extern __shared__ __half sm[];
    const int tid = threadIdx.x, lane = tid & 31, wid = tid >> 5;
    const int row0 = blockIdx.x * TILE_M;
    const int warp_m = wid & 3, warp_n = wid >> 2;

    float acc[16][4];
#pragma unroll
    for (int t = 0; t < 16; t++)
#pragma unroll
        for (int j = 0; j < 4; j++) acc[t][j] = 0.f;

    const int ar = tid >> 1, ah_ = tid & 1;
    const int agr = row0 + ar;
    const int wc0 = (tid & 15) * 8;

    uint32_t h[16];

#define LOAD_A(c) do {                                                          \
        const int k0 = (c) * KC;                                                \
        if (agr < N_NODES) {                                                    \
            const float4* src = (const float4*)&A[(size_t)agr * IN_F + k0 + ah_ * 32]; \
            _Pragma("unroll")                                                   \
            for (int q = 0; q < 8; q++) {                                       \
                float4 v = src[q];                                              \
                __half2 p0 = __floats2half2_rn(v.x, v.y);                       \
                __half2 p1 = __floats2half2_rn(v.z, v.w);                       \
                h[2*q]   = *reinterpret_cast<uint32_t*>(&p0);                   \
                h[2*q+1] = *reinterpret_cast<uint32_t*>(&p1);                   \
            }                                                                   \
        } else {                                                                \
            _Pragma("unroll")                                                   \
            for (int q = 0; q < 16; q++) h[q] = 0u;                             \
        }                                                                       \
    } while (0)

#define STORE_A(b) do {                                                         \
        __half* ph = &(sm + (b) * BUFE)[ar * A_LD + ah_ * 32];                  \
        *(uint4*)(ph)      = make_uint4(h[0],  h[1],  h[2],  h[3]);             \
        *(uint4*)(ph + 8)  = make_uint4(h[4],  h[5],  h[6],  h[7]);             \
        *(uint4*)(ph + 16) = make_uint4(h[8],  h[9],  h[10], h[11]);            \
        *(uint4*)(ph + 24) = make_uint4(h[12], h[13], h[14], h[15]);            \
    } while (0)

#define ISSUE_W(c, b) do {                                                      \
        const int k0 = (c) * KC;                                                \
        uint32_t wh = smem_u32(sm + (b) * BUFE + ABUF);                         \
        _Pragma("unroll")                                                       \
        for (int j = 0; j < 4; j++) {                                           \
            int wrow = (tid + 256 * j) >> 4;                                    \
            cp16(wh + (wrow * W_LD + wc0) * 2,                                  \
                 &g_wfh[(size_t)(k0 + wrow) * HID + wc0]);                      \
        }                                                                       \
        cp_commit();                                                            \
    } while (0)

    ISSUE_W(0, 0);
    LOAD_A(0);
    STORE_A(0);
    cp_wait_all();
    __syncthreads();

    for (int c = 0; c < NCHUNK; c++) {
        const int buf = c & 1;
        if (c < NCHUNK - 1) {
            ISSUE_W(c + 1, buf ^ 1);
            LOAD_A(c + 1);
        }

        const __half* Ah = sm + buf * BUFE;
        const __half* Wh = Ah + ABUF;

#pragma unroll
        for (int ks = 0; ks < 4; ks++) {
            uint32_t a_h[2][4];
#pragma unroll
            for (int mi = 0; mi < 2; mi++) {
                uint32_t aoff = (warp_m * 32 + mi * 16 + (lane & 15)) * A_LD
                              + ks * 16 + (lane >> 4) * 8;
                ldsm4(a_h[mi], smem_u32(&Ah[aoff]));
            }
#pragma unroll
            for (int nt = 0; nt < 4; nt++) {
                uint32_t b_h[4];
                uint32_t woff = (ks * 16 + (lane & 15)) * W_LD
                              + warp_n * 64 + nt * 16 + (lane >> 4) * 8;
                ldsm4t(b_h, smem_u32(&Wh[woff]));
#pragma unroll
                for (int mi = 0; mi < 2; mi++) {
                    int t = mi * 8 + nt * 2;
                    mma16816(acc[t],     a_h[mi], b_h);
                    mma16816(acc[t + 1], a_h[mi], b_h + 2);
                }
            }
        }
        if (c < NCHUNK - 1) {
            STORE_A(buf ^ 1);
            cp_wait_all();
        }
        __syncthreads();
    }

    // ---- epilogue: fp16 g_xh + fused attention dots ----
    float sd[2][2] = {{0.f, 0.f}, {0.f, 0.f}};
    float dd[2][2] = {{0.f, 0.f}, {0.f, 0.f}};
#pragma unroll
    for (int mi = 0; mi < 2; mi++) {
        const int rlo = row0 + warp_m * 32 + mi * 16 + (lane >> 2);
        const int rhi = rlo + 8;
#pragma unroll
        for (int nt = 0; nt < 4; nt++) {
#pragma unroll
            for (int hh = 0; hh < 2; hh++) {
                int t = mi * 8 + nt * 2 + hh;
                int col = warp_n * 64 + nt * 16 + hh * 8 + (lane & 3) * 2;
                float as0 = __ldg(&attsrc[col]), as1 = __ldg(&attsrc[col + 1]);
                float ad0 = __ldg(&attdst[col]), ad1 = __ldg(&attdst[col + 1]);
                float2 v0 = make_float2(acc[t][0], acc[t][1]);
                float2 v1 = make_float2(acc[t][2], acc[t][3]);
                sd[mi][0] += v0.x * as0 + v0.y * as1;
                dd[mi][0] += v0.x * ad0 + v0.y * ad1;
                sd[mi][1] += v1.x * as0 + v1.y * as1;
                dd[mi][1] += v1.x * ad0 + v1.y * ad1;
                if (rlo < N_NODES) {
                    __half2 p = __float22half2_rn(v0);
                    *(uint32_t*)&g_xh[(size_t)rlo * HID + col] = *(uint32_t*)&p;
                }
                if (rhi < N_NODES) {
                    __half2 p = __float22half2_rn(v1);
                    *(uint32_t*)&g_xh[(size_t)rhi * HID + col] = *(uint32_t*)&p;
                }
            }
        }
    }
#pragma unroll
    for (int o = 1; o <= 2; o <<= 1) {
#pragma unroll
        for (int mi = 0; mi < 2; mi++)
#pragma unroll
            for (int hh = 0; hh < 2; hh++) {
                sd[mi][hh] += __shfl_xor_sync(0xffffffffu, sd[mi][hh], o);
                dd[mi][hh] += __shfl_xor_sync(0xffffffffu, dd[mi][hh], o);
            }
    }
    float* sdp = (float*)sm;
    float* ddp = sdp + 256;
    if ((lane & 3) == 0) {
#pragma unroll
        for (int mi = 0; mi < 2; mi++)
#pragma unroll
            for (int hh = 0; hh < 2; hh++) {
                int rt = warp_m * 32 + mi * 16 + (lane >> 2) + hh * 8;
                sdp[rt * 2 + warp_n] = sd[mi][hh];
                ddp[rt * 2 + warp_n] = dd[mi][hh];
            }
    }
    __syncthreads();
    if (tid < 128) {
        int gr = row0 + tid;
        if (gr < N_NODES) {
            g_asrc[gr] = sdp[tid * 2] + sdp[tid * 2 + 1];
            g_adst[gr] = ddp[tid * 2] + ddp[tid * 2 + 1];
        }
    }
}

// ---------------- histogram (real edges only; self-loops analytic) ----------------
__global__ void hist_kernel(const void* __restrict__ adj) {
    int i = blockIdx.x * blockDim.x + threadIdx.x;
    if (i >= N_EDGES) return;
    int is64 = g_is64;
    int d = load_adj(adj, (long long)N_EDGES + i, is64);
    atomicAdd(&g_deg[d], 1);
}

// ---------------- scan: per-block sums, then fused base+scan ----------------
__global__ void __launch_bounds__(1024) scan1_kernel() {
    __shared__ int ws[32];
    int tid = threadIdx.x, lane = tid & 31, wid = tid >> 5;
    int i = blockIdx.x * 1024 + tid;
    int v = (i < N_NODES) ? g_deg[i] : 0;
#pragma unroll
    for (int o = 16; o; o >>= 1) v += __shfl_down_sync(0xffffffffu, v, o);
    if (lane == 0) ws[wid] = v;
    __syncthreads();
    if (wid == 0) {
        int s = ws[lane];
#pragma unroll
        for (int o = 16; o; o >>= 1) s += __shfl_down_sync(0xffffffffu, s, o);
        if (lane == 0) g_part[blockIdx.x] = s;
    }
}
__global__ void __launch_bounds__(1024) scan2_kernel() {
    __shared__ int ws[32];
    __shared__ int s_base;
    int tid = threadIdx.x, lane = tid & 31, wid = tid >> 5;
    // block base = sum of g_part[j < blockIdx.x]
    {
        int p = (tid < blockIdx.x) ? g_part[tid] : 0;   // blockIdx.x <= 97 < 1024
#pragma unroll
        for (int o = 16; o; o >>= 1) p += __shfl_down_sync(0xffffffffu, p, o);
        if (lane == 0) ws[wid] = p;
        __syncthreads();
        if (wid == 0) {
            int s = ws[lane];
#pragma unroll
            for (int o = 16; o; o >>= 1) s += __shfl_down_sync(0xffffffffu, s, o);
            if (lane == 0) s_base = s;
        }
        __syncthreads();
    }
    int i = blockIdx.x * 1024 + tid;
    int v = (i < N_NODES) ? g_deg[i] : 0;
    int incl = v;
#pragma unroll
    for (int o = 1; o < 32; o <<= 1) {
        int t = __shfl_up_sync(0xffffffffu, incl, o);
        if (lane >= o) incl += t;
    }
    __syncthreads();
    if (lane == 31) ws[wid] = incl;
    __syncthreads();
    if (wid == 0) {
        int s = ws[lane];
        int sc = s;
#pragma unroll
        for (int o = 1; o < 32; o <<= 1) {
            int t = __shfl_up_sync(0xffffffffu, sc, o);
            if (lane >= o) sc += t;
        }
        ws[lane] = sc - s;
    }
    __syncthreads();
    int excl = s_base + ws[wid] + incl - v;
    if (i < N_NODES) {
        g_off[i] = excl;
        g_cur[i] = excl;
        if (i == N_NODES - 1) g_off[N_NODES] = excl + v;
    }
}

// ---------------- scatter (real edges only) ----------------
__global__ void scatter_kernel(const void* __restrict__ adj) {
    int i = blockIdx.x * blockDim.x + threadIdx.x;
    if (i >= N_EDGES) return;
    int is64 = g_is64;
    int s = load_adj(adj, i, is64);
    int d = load_adj(adj, (long long)N_EDGES + i, is64);
    float e = g_asrc[s] + g_adst[d];
    e = (e > 0.f) ? e : 0.2f * e;
    float ex = __expf(e);
    int pos = atomicAdd(&g_cur[d], 1);
    g_edge[pos] = make_int2(s, __float_as_int(ex));
}

// ---------------- aggregation (fp16 gather; self-loop analytic) ----------------
__global__ void agg_kernel(const float* __restrict__ bias, float* __restrict__ out) {
    int w = (blockIdx.x * blockDim.x + threadIdx.x) >> 5;
    int lane = threadIdx.x & 31;
    if (w >= N_NODES) return;
    int st = g_off[w], en = g_off[w + 1];
    // self-loop term
    float es = g_asrc[w] + g_adst[w];
    es = (es > 0.f) ? es : 0.2f * es;
    float ssum = __expf(es);
    float4 acc;
    {
        uint2 raw = *(const uint2*)&g_xh[(size_t)w * HID + lane * 4];
        float2 f0 = __half22float2(*reinterpret_cast<__half2*>(&raw.x));
        float2 f1 = __half22float2(*reinterpret_cast<__half2*>(&raw.y));
        acc = make_float4(ssum * f0.x, ssum * f0.y, ssum * f1.x, ssum * f1.y);
    }
    for (int j = st; j < en; j++) {
        int2 se = g_edge[j];
        float ex = __int_as_float(se.y);
        uint2 raw = *(const uint2*)&g_xh[(size_t)se.x * HID + lane * 4];
        float2 f0 = __half22float2(*reinterpret_cast<__half2*>(&raw.x));
        float2 f1 = __half22float2(*reinterpret_cast<__half2*>(&raw.y));
        ssum += ex;
        acc.x += ex * f0.x;
        acc.y += ex * f0.y;
        acc.z += ex * f1.x;
        acc.w += ex * f1.y;
    }
    float inv = 1.f / (ssum + 1e-16f);
    float4 b = *(const float4*)&bias[lane * 4];
    float4 o;
    o.x = acc.x * inv + b.x;
    o.y = acc.y * inv + b.y;
    o.z = acc.z * inv + b.z;
    o.w = acc.w * inv + b.w;
    o.x = (o.x > 0.f) ? o.x : 0.25f * o.x;
    o.y = (o.y > 0.f) ? o.y : 0.25f * o.y;
    o.z = (o.z > 0.f) ? o.z : 0.25f * o.z;
    o.w = (o.w > 0.f) ? o.w : 0.25f * o.w;
    *(float4*)&out[(size_t)w * HID + lane * 4] = o;
}

// ---------------- launcher ----------------
extern "C" void kernel_launch(void* const* d_in, const int* in_sizes, int n_in,
                              void* d_out, int out_size) {
    const float* data   = (const float*)d_in[0];
    const void*  adj    = (const void*)d_in[1];
    const float* W      = (const float*)d_in[2];
    const float* attsrc = (const float*)d_in[3];
    const float* attdst = (const float*)d_in[4];
    const float* bias   = (const float*)d_in[5];
    float* out = (float*)d_out;

    cudaFuncSetAttribute(gemm_kernel, cudaFuncAttributeMaxDynamicSharedMemorySize, S_BYTES);

    prep_kernel<<<(N_NODES + 255) / 256, 256>>>(adj, W);
    gemm_kernel<<<(N_NODES + TILE_M - 1) / TILE_M, 256, S_BYTES>>>(data, attsrc, attdst);
    hist_kernel<<<(N_EDGES + 255) / 256, 256>>>(adj);
    scan1_kernel<<<NBLK_SCAN, 1024>>>();
    scan2_kernel<<<NBLK_SCAN, 1024>>>();
    scatter_kernel<<<(N_EDGES + 255) / 256, 256>>>(adj);
    agg_kernel<<<(N_NODES * 32 + 255) / 256, 256>>>(bias, out);
}

// round 15
// speedup vs baseline: 1.0916x; 1.0274x over previous
#include <cuda_runtime.h>
#include <cuda_bf16.h>
#include <cuda_fp16.h>
#include <cstdint>

#define N_NODES 100000
#define N_EDGES 3200000
#define IN_F    512
#define HID     128
#define TILE_M  128
#define KC      64
#define NCHUNK  (IN_F / KC)     // 8
#define NBLK_SCAN 98

#define A_LD 72                       // elems (64 + 8 pad)
#define W_LD 136                      // elems (128 + 8 pad)
#define ABUF (TILE_M * A_LD)          // 9216 elems
#define WBUF (KC * W_LD)              // 8704 elems
#define BUFE (ABUF + WBUF)            // 17920 elems per buffer
#define S_BYTES (2 * BUFE * 2)        // 71680 bytes

// ---------------- scratch ----------------
__device__ __align__(16) __half g_xh[(size_t)N_NODES * HID];   // fp16 feature cache
__device__ float g_asrc[N_NODES];
__device__ float g_adst[N_NODES];
__device__ int   g_deg[N_NODES];
__device__ int   g_off[N_NODES + 1];
__device__ int   g_cur[N_NODES];
__device__ __align__(16) int2 g_edge[N_EDGES];   // (src, exp-bits) sorted by dst
__device__ int   g_is64;
__device__ __align__(16) __half g_wfh[IN_F * HID];   // W fp16 [k][n]
__device__ int   g_part[128];

// ---------------- helpers ----------------
__device__ __forceinline__ uint32_t smem_u32(const void* p) {
    uint32_t a;
    asm("{ .reg .u64 t; cvta.to.shared.u64 t, %1; cvt.u32.u64 %0, t; }" : "=r"(a) : "l"(p));
    return a;
}
__device__ __forceinline__ void ldsm4(uint32_t* r, uint32_t addr) {
    asm volatile("ldmatrix.sync.aligned.m8n8.x4.shared.b16 {%0,%1,%2,%3}, [%4];"
                 : "=r"(r[0]), "=r"(r[1]), "=r"(r[2]), "=r"(r[3]) : "r"(addr));
}
__device__ __forceinline__ void ldsm4t(uint32_t* r, uint32_t addr) {
    asm volatile("ldmatrix.sync.aligned.m8n8.x4.trans.shared.b16 {%0,%1,%2,%3}, [%4];"
                 : "=r"(r[0]), "=r"(r[1]), "=r"(r[2]), "=r"(r[3]) : "r"(addr));
}
__device__ __forceinline__ void mma16816(float* c, const uint32_t* a, const uint32_t* b) {
    asm volatile("mma.sync.aligned.m16n8k16.row.col.f32.f16.f16.f32 "
                 "{%0,%1,%2,%3}, {%4,%5,%6,%7}, {%8,%9}, {%0,%1,%2,%3};"
                 : "+f"(c[0]), "+f"(c[1]), "+f"(c[2]), "+f"(c[3])
                 : "r"(a[0]), "r"(a[1]), "r"(a[2]), "r"(a[3]), "r"(b[0]), "r"(b[1]));
}
__device__ __forceinline__ void cp16(uint32_t dst, const void* src) {
    asm volatile("cp.async.ca.shared.global [%0], [%1], 16;" :: "r"(dst), "l"(src));
}
__device__ __forceinline__ void cp_commit() {
    asm volatile("cp.async.commit_group;" ::: "memory");
}
__device__ __forceinline__ void cp_wait_all() {
    asm volatile("cp.async.wait_group 0;" ::: "memory");
}

// ---------------- adj helpers ----------------
__device__ __forceinline__ int load_adj(const void* adj, long long i, int is64) {
    if (is64) return (int)((const long long*)adj)[i];
    return ((const int*)adj)[i];
}

// ---------------- fused prep: zero degrees + W fp16 + dtype detect ----------------
__global__ void prep_kernel(const void* adj, const float* __restrict__ W) {
    int i = blockIdx.x * blockDim.x + threadIdx.x;
    if (i < N_NODES) g_deg[i] = 0;
    if (i < IN_F * HID) g_wfh[i] = __float2half_rn(W[i]);
    if (i == 0) {
        const int* p = (const int*)adj;
        int acc = 0;
#pragma unroll
        for (int k = 0; k < 64; k++) acc |= p[2 * k + 1];
        for (int k = 0; k < 64; k++) acc |= p[2 * (k * 9973 + 1000) + 1];
        g_is64 = (acc == 0) ? 1 : 0;
    }
}

// ---------------- pipelined fp16 HMMA GEMM, 2 CTAs/SM ----------------
__global__ void __launch_bounds__(256, 2) gemm_kernel(const float* __restrict__ A,
                                                      const float* __restrict__ attsrc,
                                                      const float* __restrict__ attdst) {
    extern __shared__ __half sm[];
    const int tid = threadIdx.x, lane = tid & 31, wid = tid >> 5;
    const int row0 = blockIdx.x * TILE_M;
    const int warp_m = wid & 3, warp_n = wid >> 2;

    float acc[16][4];
#pragma unroll
    for (int t = 0; t < 16; t++)
#pragma unroll
        for (int j = 0; j < 4; j++) acc[t][j] = 0.f;

    const int ar = tid >> 1, ah_ = tid & 1;
    const int agr = row0 + ar;
    const int wc0 = (tid & 15) * 8;

    uint32_t h[16];

#define LOAD_A(c) do {                                                          \
        const int k0 = (c) * KC;                                                \
        if (agr < N_NODES) {                                                    \
            const float4* src = (const float4*)&A[(size_t)agr * IN_F + k0 + ah_ * 32]; \
            _Pragma("unroll")                                                   \
            for (int q = 0; q < 8; q++) {                                       \
                float4 v = src[q];                                              \
                __half2 p0 = __floats2half2_rn(v.x, v.y);                       \
                __half2 p1 = __floats2half2_rn(v.z, v.w);                       \
                h[2*q]   = *reinterpret_cast<uint32_t*>(&p0);                   \
                h[2*q+1] = *reinterpret_cast<uint32_t*>(&p1);                   \
            }                                                                   \
        } else {                                                                \
            _Pragma("unroll")                                                   \
            for (int q = 0; q < 16; q++) h[q] = 0u;                             \
        }                                                                       \
    } while (0)

#define STORE_A(b) do {                                                         \
        __half* ph = &(sm + (b) * BUFE)[ar * A_LD + ah_ * 32];                  \
        *(uint4*)(ph)      = make_uint4(h[0],  h[1],  h[2],  h[3]);             \
        *(uint4*)(ph + 8)  = make_uint4(h[4],  h[5],  h[6],  h[7]);             \
        *(uint4*)(ph + 16) = make_uint4(h[8],  h[9],  h[10], h[11]);            \
        *(uint4*)(ph + 24) = make_uint4(h[12], h[13], h[14], h[15]);            \
    } while (0)

#define ISSUE_W(c, b) do {                                                      \
        const int k0 = (c) * KC;                                                \
        uint32_t wh = smem_u32(sm + (b) * BUFE + ABUF);                         \
        _Pragma("unroll")                                                       \
        for (int j = 0; j < 4; j++) {                                           \
            int wrow = (tid + 256 * j) >> 4;                                    \
            cp16(wh + (wrow * W_LD + wc0) * 2,                                  \
                 &g_wfh[(size_t)(k0 + wrow) * HID + wc0]);                      \
        }                                                                       \
        cp_commit();                                                            \
    } while (0)

    ISSUE_W(0, 0);
    LOAD_A(0);
    STORE_A(0);
    cp_wait_all();
    __syncthreads();

    for (int c = 0; c < NCHUNK; c++) {
        const int buf = c & 1;
        if (c < NCHUNK - 1) {
            ISSUE_W(c + 1, buf ^ 1);
            LOAD_A(c + 1);
        }

        const __half* Ah = sm + buf * BUFE;
        const __half* Wh = Ah + ABUF;

#pragma unroll
        for (int ks = 0; ks < 4; ks++) {
            uint32_t a_h[2][4];
#pragma unroll
            for (int mi = 0; mi < 2; mi++) {
                uint32_t aoff = (warp_m * 32 + mi * 16 + (lane & 15)) * A_LD
                              + ks * 16 + (lane >> 4) * 8;
                ldsm4(a_h[mi], smem_u32(&Ah[aoff]));
            }
#pragma unroll
            for (int nt = 0; nt < 4; nt++) {
                uint32_t b_h[4];
                uint32_t woff = (ks * 16 + (lane & 15)) * W_LD
                              + warp_n * 64 + nt * 16 + (lane >> 4) * 8;
                ldsm4t(b_h, smem_u32(&Wh[woff]));
#pragma unroll
                for (int mi = 0; mi < 2; mi++) {
                    int t = mi * 8 + nt * 2;
                    mma16816(acc[t],     a_h[mi], b_h);
                    mma16816(acc[t + 1], a_h[mi], b_h + 2);
                }
            }
        }
        if (c < NCHUNK - 1) {
            STORE_A(buf ^ 1);
            cp_wait_all();
        }
        __syncthreads();
    }

    // ---- epilogue: fp16 g_xh + fused attention dots ----
    float sd[2][2] = {{0.f, 0.f}, {0.f, 0.f}};
    float dd[2][2] = {{0.f, 0.f}, {0.f, 0.f}};
#pragma unroll
    for (int mi = 0; mi < 2; mi++) {
        const int rlo = row0 + warp_m * 32 + mi * 16 + (lane >> 2);
        const int rhi = rlo + 8;
#pragma unroll
        for (int nt = 0; nt < 4; nt++) {
#pragma unroll
            for (int hh = 0; hh < 2; hh++) {
                int t = mi * 8 + nt * 2 + hh;
                int col = warp_n * 64 + nt * 16 + hh * 8 + (lane & 3) * 2;
                float as0 = __ldg(&attsrc[col]), as1 = __ldg(&attsrc[col + 1]);
                float ad0 = __ldg(&attdst[col]), ad1 = __ldg(&attdst[col + 1]);
                float2 v0 = make_float2(acc[t][0], acc[t][1]);
                float2 v1 = make_float2(acc[t][2], acc[t][3]);
                sd[mi][0] += v0.x * as0 + v0.y * as1;
                dd[mi][0] += v0.x * ad0 + v0.y * ad1;
                sd[mi][1] += v1.x * as0 + v1.y * as1;
                dd[mi][1] += v1.x * ad0 + v1.y * ad1;
                if (rlo < N_NODES) {
                    __half2 p = __float22half2_rn(v0);
                    *(uint32_t*)&g_xh[(size_t)rlo * HID + col] = *(uint32_t*)&p;
                }
                if (rhi < N_NODES) {
                    __half2 p = __float22half2_rn(v1);
                    *(uint32_t*)&g_xh[(size_t)rhi * HID + col] = *(uint32_t*)&p;
                }
            }
        }
    }
#pragma unroll
    for (int o = 1; o <= 2; o <<= 1) {
#pragma unroll
        for (int mi = 0; mi < 2; mi++)
#pragma unroll
            for (int hh = 0; hh < 2; hh++) {
                sd[mi][hh] += __shfl_xor_sync(0xffffffffu, sd[mi][hh], o);
                dd[mi][hh] += __shfl_xor_sync(0xffffffffu, dd[mi][hh], o);
            }
    }
    float* sdp = (float*)sm;
    float* ddp = sdp + 256;
    if ((lane & 3) == 0) {
#pragma unroll
        for (int mi = 0; mi < 2; mi++)
#pragma unroll
            for (int hh = 0; hh < 2; hh++) {
                int rt = warp_m * 32 + mi * 16 + (lane >> 2) + hh * 8;
                sdp[rt * 2 + warp_n] = sd[mi][hh];
                ddp[rt * 2 + warp_n] = dd[mi][hh];
            }
    }
    __syncthreads();
    if (tid < 128) {
        int gr = row0 + tid;
        if (gr < N_NODES) {
            g_asrc[gr] = sdp[tid * 2] + sdp[tid * 2 + 1];
            g_adst[gr] = ddp[tid * 2] + ddp[tid * 2 + 1];
        }
    }
}

// ---------------- histogram (real edges only; self-loops analytic) ----------------
__global__ void hist_kernel(const void* __restrict__ adj) {
    int i = blockIdx.x * blockDim.x + threadIdx.x;
    if (i >= N_EDGES) return;
    int is64 = g_is64;
    int d = load_adj(adj, (long long)N_EDGES + i, is64);
    atomicAdd(&g_deg[d], 1);
}

// ---------------- scan: per-block sums, then fused base+scan ----------------
__global__ void __launch_bounds__(1024) scan1_kernel() {
    __shared__ int ws[32];
    int tid = threadIdx.x, lane = tid & 31, wid = tid >> 5;
    int i = blockIdx.x * 1024 + tid;
    int v = (i < N_NODES) ? g_deg[i] : 0;
#pragma unroll
    for (int o = 16; o; o >>= 1) v += __shfl_down_sync(0xffffffffu, v, o);
    if (lane == 0) ws[wid] = v;
    __syncthreads();
    if (wid == 0) {
        int s = ws[lane];
#pragma unroll
        for (int o = 16; o; o >>= 1) s += __shfl_down_sync(0xffffffffu, s, o);
        if (lane == 0) g_part[blockIdx.x] = s;
    }
}
__global__ void __launch_bounds__(1024) scan2_kernel() {
    __shared__ int ws[32];
    __shared__ int s_base;
    int tid = threadIdx.x, lane = tid & 31, wid = tid >> 5;
    {
        int p = (tid < blockIdx.x) ? g_part[tid] : 0;
#pragma unroll
        for (int o = 16; o; o >>= 1) p += __shfl_down_sync(0xffffffffu, p, o);
        if (lane == 0) ws[wid] = p;
        __syncthreads();
        if (wid == 0) {
            int s = ws[lane];
#pragma unroll
            for (int o = 16; o; o >>= 1) s += __shfl_down_sync(0xffffffffu, s, o);
            if (lane == 0) s_base = s;
        }
        __syncthreads();
    }
    int i = blockIdx.x * 1024 + tid;
    int v = (i < N_NODES) ? g_deg[i] : 0;
    int incl = v;
#pragma unroll
    for (int o = 1; o < 32; o <<= 1) {
        int t = __shfl_up_sync(0xffffffffu, incl, o);
        if (lane >= o) incl += t;
    }
    __syncthreads();
    if (lane == 31) ws[wid] = incl;
    __syncthreads();
    if (wid == 0) {
        int s = ws[lane];
        int sc = s;
#pragma unroll
        for (int o = 1; o < 32; o <<= 1) {
            int t = __shfl_up_sync(0xffffffffu, sc, o);
            if (lane >= o) sc += t;
        }
        ws[lane] = sc - s;
    }
    __syncthreads();
    int excl = s_base + ws[wid] + incl - v;
    if (i < N_NODES) {
        g_off[i] = excl;
        g_cur[i] = excl;
        if (i == N_NODES - 1) g_off[N_NODES] = excl + v;
    }
}

// ---------------- scatter (real edges only) ----------------
__global__ void scatter_kernel(const void* __restrict__ adj) {
    int i = blockIdx.x * blockDim.x + threadIdx.x;
    if (i >= N_EDGES) return;
    int is64 = g_is64;
    int s = load_adj(adj, i, is64);
    int d = load_adj(adj, (long long)N_EDGES + i, is64);
    float e = g_asrc[s] + g_adst[d];
    e = (e > 0.f) ? e : 0.2f * e;
    float ex = __expf(e);
    int pos = atomicAdd(&g_cur[d], 1);
    g_edge[pos] = make_int2(s, __float_as_int(ex));
}

// ---------------- aggregation (fp16 gather; self-loop analytic) ----------------
__global__ void agg_kernel(const float* __restrict__ bias, float* __restrict__ out) {
    int w = (blockIdx.x * blockDim.x + threadIdx.x) >> 5;
    int lane = threadIdx.x & 31;
    if (w >= N_NODES) return;
    int st = g_off[w], en = g_off[w + 1];
    float es = g_asrc[w] + g_adst[w];
    es = (es > 0.f) ? es : 0.2f * es;
    float ssum = __expf(es);
    float4 acc;
    {
        uint2 raw = *(const uint2*)&g_xh[(size_t)w * HID + lane * 4];
        float2 f0 = __half22float2(*reinterpret_cast<__half2*>(&raw.x));
        float2 f1 = __half22float2(*reinterpret_cast<__half2*>(&raw.y));
        acc = make_float4(ssum * f0.x, ssum * f0.y, ssum * f1.x, ssum * f1.y);
    }
    for (int j = st; j < en; j++) {
        int2 se = g_edge[j];
        float ex = __int_as_float(se.y);
        uint2 raw = *(const uint2*)&g_xh[(size_t)se.x * HID + lane * 4];
        float2 f0 = __half22float2(*reinterpret_cast<__half2*>(&raw.x));
        float2 f1 = __half22float2(*reinterpret_cast<__half2*>(&raw.y));
        ssum += ex;
        acc.x += ex * f0.x;
        acc.y += ex * f0.y;
        acc.z += ex * f1.x;
        acc.w += ex * f1.y;
    }
    float inv = 1.f / (ssum + 1e-16f);
    float4 b = *(const float4*)&bias[lane * 4];
    float4 o;
    o.x = acc.x * inv + b.x;
    o.y = acc.y * inv + b.y;
    o.z = acc.z * inv + b.z;
    o.w = acc.w * inv + b.w;
    o.x = (o.x > 0.f) ? o.x : 0.25f * o.x;
    o.y = (o.y > 0.f) ? o.y : 0.25f * o.y;
    o.z = (o.z > 0.f) ? o.z : 0.25f * o.z;
    o.w = (o.w > 0.f) ? o.w : 0.25f * o.w;
    *(float4*)&out[(size_t)w * HID + lane * 4] = o;
}

// ---------------- launcher: fork hist/scan chain parallel to GEMM ----------------
extern "C" void kernel_launch(void* const* d_in, const int* in_sizes, int n_in,
                              void* d_out, int out_size) {
    const float* data   = (const float*)d_in[0];
    const void*  adj    = (const void*)d_in[1];
    const float* W      = (const float*)d_in[2];
    const float* attsrc = (const float*)d_in[3];
    const float* attdst = (const float*)d_in[4];
    const float* bias   = (const float*)d_in[5];
    float* out = (float*)d_out;

    cudaFuncSetAttribute(gemm_kernel, cudaFuncAttributeMaxDynamicSharedMemorySize, S_BYTES);

    // fork/join resources; created per call, intentionally not destroyed
    // (destroying objects referenced by an in-progress stream capture is
    // unsafe; kernel_launch runs ~2x total, replays use the graph only).
    cudaStream_t s2;
    cudaStreamCreateWithFlags(&s2, cudaStreamNonBlocking);
    cudaEvent_t ev_fork, ev_join;
    cudaEventCreateWithFlags(&ev_fork, cudaEventDisableTiming);
    cudaEventCreateWithFlags(&ev_join, cudaEventDisableTiming);

    prep_kernel<<<(N_NODES + 255) / 256, 256>>>(adj, W);

    // fork: hist/scan chain depends only on prep + adj
    cudaEventRecord(ev_fork, 0);
    cudaStreamWaitEvent(s2, ev_fork, 0);
    hist_kernel<<<(N_EDGES + 255) / 256, 256, 0, s2>>>(adj);
    scan1_kernel<<<NBLK_SCAN, 1024, 0, s2>>>();
    scan2_kernel<<<NBLK_SCAN, 1024, 0, s2>>>();
    cudaEventRecord(ev_join, s2);

    // main stream: GEMM runs concurrently with the fork
    gemm_kernel<<<(N_NODES + TILE_M - 1) / TILE_M, 256, S_BYTES>>>(data, attsrc, attdst);

    // join: scatter needs both gemm (asrc/adst) and scan2 (offsets)
    cudaStreamWaitEvent(0, ev_join, 0);
    scatter_kernel<<<(N_EDGES + 255) / 256, 256>>>(adj);
    agg_kernel<<<(N_NODES * 32 + 255) / 256, 256>>>(bias, out);
}

// round 16
// speedup vs baseline: 1.1296x; 1.0348x over previous
#include <cuda_runtime.h>
#include <cuda_bf16.h>
#include <cuda_fp16.h>
#include <cstdint>

#define N_NODES 100000
#define N_EDGES 3200000
#define IN_F    512
#define HID     128
#define TILE_M  128
#define KC      64
#define NCHUNK  (IN_F / KC)     // 8
#define NBLK_SCAN 98

#define A_LD 72                       // elems (64 + 8 pad)
#define W_LD 136                      // elems (128 + 8 pad)
#define ABUF (TILE_M * A_LD)          // 9216 elems
#define WBUF (KC * W_LD)              // 8704 elems
#define BUFE (ABUF + WBUF)            // 17920 elems per buffer
#define S_BYTES (2 * BUFE * 2)        // 71680 bytes

// ---------------- scratch ----------------
__device__ __align__(16) __half g_xh[(size_t)N_NODES * HID];   // fp16 feature cache
__device__ float g_asrc[N_NODES];
__device__ float g_adst[N_NODES];
__device__ int   g_deg[N_NODES];
__device__ int   g_off[N_NODES + 1];
__device__ int   g_cur[N_NODES];
__device__ __align__(16) int g_src[N_EDGES];   // src ids sorted by dst
__device__ int   g_is64;
__device__ __align__(16) __half g_wfh[IN_F * HID];   // W fp16 [k][n]
__device__ int   g_part[128];

// ---------------- helpers ----------------
__device__ __forceinline__ uint32_t smem_u32(const void* p) {
    uint32_t a;
    asm("{ .reg .u64 t; cvta.to.shared.u64 t, %1; cvt.u32.u64 %0, t; }" : "=r"(a) : "l"(p));
    return a;
}
__device__ __forceinline__ void ldsm4(uint32_t* r, uint32_t addr) {
    asm volatile("ldmatrix.sync.aligned.m8n8.x4.shared.b16 {%0,%1,%2,%3}, [%4];"
                 : "=r"(r[0]), "=r"(r[1]), "=r"(r[2]), "=r"(r[3]) : "r"(addr));
}
__device__ __forceinline__ void ldsm4t(uint32_t* r, uint32_t addr) {
    asm volatile("ldmatrix.sync.aligned.m8n8.x4.trans.shared.b16 {%0,%1,%2,%3}, [%4];"
                 : "=r"(r[0]), "=r"(r[1]), "=r"(r[2]), "=r"(r[3]) : "r"(addr));
}
__device__ __forceinline__ void mma16816(float* c, const uint32_t* a, const uint32_t* b) {
    asm volatile("mma.sync.aligned.m16n8k16.row.col.f32.f16.f16.f32 "
                 "{%0,%1,%2,%3}, {%4,%5,%6,%7}, {%8,%9}, {%0,%1,%2,%3};"
                 : "+f"(c[0]), "+f"(c[1]), "+f"(c[2]), "+f"(c[3])
                 : "r"(a[0]), "r"(a[1]), "r"(a[2]), "r"(a[3]), "r"(b[0]), "r"(b[1]));
}
__device__ __forceinline__ void cp16(uint32_t dst, const void* src) {
    asm volatile("cp.async.ca.shared.global [%0], [%1], 16;" :: "r"(dst), "l"(src));
}
__device__ __forceinline__ void cp_commit() {
    asm volatile("cp.async.commit_group;" ::: "memory");
}
__device__ __forceinline__ void cp_wait_all() {
    asm volatile("cp.async.wait_group 0;" ::: "memory");
}

// ---------------- adj helpers ----------------
__device__ __forceinline__ int load_adj(const void* adj, long long i, int is64) {
    if (is64) return (int)((const long long*)adj)[i];
    return ((const int*)adj)[i];
}

// ---------------- fused prep: zero degrees + W fp16 + dtype detect ----------------
__global__ void prep_kernel(const void* adj, const float* __restrict__ W) {
    int i = blockIdx.x * blockDim.x + threadIdx.x;
    if (i < N_NODES) g_deg[i] = 0;
    if (i < IN_F * HID) g_wfh[i] = __float2half_rn(W[i]);
    if (i == 0) {
        const int* p = (const int*)adj;
        int acc = 0;
#pragma unroll
        for (int k = 0; k < 64; k++) acc |= p[2 * k + 1];
        for (int k = 0; k < 64; k++) acc |= p[2 * (k * 9973 + 1000) + 1];
        g_is64 = (acc == 0) ? 1 : 0;
    }
}

// ---------------- pipelined fp16 HMMA GEMM, 2 CTAs/SM ----------------
__global__ void __launch_bounds__(256, 2) gemm_kernel(const float* __restrict__ A,
                                                      const float* __restrict__ attsrc,
                                                      const float* __restrict__ attdst) {
    extern __shared__ __half sm[];
    const int tid = threadIdx.x, lane = tid & 31, wid = tid >> 5;
    const int row0 = blockIdx.x * TILE_M;
    const int warp_m = wid & 3, warp_n = wid >> 2;

    float acc[16][4];
#pragma unroll
    for (int t = 0; t < 16; t++)
#pragma unroll
        for (int j = 0; j < 4; j++) acc[t][j] = 0.f;

    const int ar = tid >> 1, ah_ = tid & 1;
    const int agr = row0 + ar;
    const int wc0 = (tid & 15) * 8;

    uint32_t h[16];

#define LOAD_A(c) do {                                                          \
        const int k0 = (c) * KC;                                                \
        if (agr < N_NODES) {                                                    \
            const float4* src = (const float4*)&A[(size_t)agr * IN_F + k0 + ah_ * 32]; \
            _Pragma("unroll")                                                   \
            for (int q = 0; q < 8; q++) {                                       \
                float4 v = src[q];                                              \
                __half2 p0 = __floats2half2_rn(v.x, v.y);                       \
                __half2 p1 = __floats2half2_rn(v.z, v.w);                       \
                h[2*q]   = *reinterpret_cast<uint32_t*>(&p0);                   \
                h[2*q+1] = *reinterpret_cast<uint32_t*>(&p1);                   \
            }                                                                   \
        } else {                                                                \
            _Pragma("unroll")                                                   \
            for (int q = 0; q < 16; q++) h[q] = 0u;                             \
        }                                                                       \
    } while (0)

#define STORE_A(b) do {                                                         \
        __half* ph = &(sm + (b) * BUFE)[ar * A_LD + ah_ * 32];                  \
        *(uint4*)(ph)      = make_uint4(h[0],  h[1],  h[2],  h[3]);             \
        *(uint4*)(ph + 8)  = make_uint4(h[4],  h[5],  h[6],  h[7]);             \
        *(uint4*)(ph + 16) = make_uint4(h[8],  h[9],  h[10], h[11]);            \
        *(uint4*)(ph + 24) = make_uint4(h[12], h[13], h[14], h[15]);            \
    } while (0)

#define ISSUE_W(c, b) do {                                                      \
        const int k0 = (c) * KC;                                                \
        uint32_t wh = smem_u32(sm + (b) * BUFE + ABUF);                         \
        _Pragma("unroll")                                                       \
        for (int j = 0; j < 4; j++) {                                           \
            int wrow = (tid + 256 * j) >> 4;                                    \
            cp16(wh + (wrow * W_LD + wc0) * 2,                                  \
                 &g_wfh[(size_t)(k0 + wrow) * HID + wc0]);                      \
        }                                                                       \
        cp_commit();                                                            \
    } while (0)

    ISSUE_W(0, 0);
    LOAD_A(0);
    STORE_A(0);
    cp_wait_all();
    __syncthreads();

    for (int c = 0; c < NCHUNK; c++) {
        const int buf = c & 1;
        if (c < NCHUNK - 1) {
            ISSUE_W(c + 1, buf ^ 1);
            LOAD_A(c + 1);
        }

        const __half* Ah = sm + buf * BUFE;
        const __half* Wh = Ah + ABUF;

#pragma unroll
        for (int ks = 0; ks < 4; ks++) {
            uint32_t a_h[2][4];
#pragma unroll
            for (int mi = 0; mi < 2; mi++) {
                uint32_t aoff = (warp_m * 32 + mi * 16 + (lane & 15)) * A_LD
                              + ks * 16 + (lane >> 4) * 8;
                ldsm4(a_h[mi], smem_u32(&Ah[aoff]));
            }
#pragma unroll
            for (int nt = 0; nt < 4; nt++) {
                uint32_t b_h[4];
                uint32_t woff = (ks * 16 + (lane & 15)) * W_LD
                              + warp_n * 64 + nt * 16 + (lane >> 4) * 8;
                ldsm4t(b_h, smem_u32(&Wh[woff]));
#pragma unroll
                for (int mi = 0; mi < 2; mi++) {
                    int t = mi * 8 + nt * 2;
                    mma16816(acc[t],     a_h[mi], b_h);
                    mma16816(acc[t + 1], a_h[mi], b_h + 2);
                }
            }
        }
        if (c < NCHUNK - 1) {
            STORE_A(buf ^ 1);
            cp_wait_all();
        }
        __syncthreads();
    }

    // ---- epilogue: fp16 g_xh + fused attention dots ----
    float sd[2][2] = {{0.f, 0.f}, {0.f, 0.f}};
    float dd[2][2] = {{0.f, 0.f}, {0.f, 0.f}};
#pragma unroll
    for (int mi = 0; mi < 2; mi++) {
        const int rlo = row0 + warp_m * 32 + mi * 16 + (lane >> 2);
        const int rhi = rlo + 8;
#pragma unroll
        for (int nt = 0; nt < 4; nt++) {
#pragma unroll
            for (int hh = 0; hh < 2; hh++) {
                int t = mi * 8 + nt * 2 + hh;
                int col = warp_n * 64 + nt * 16 + hh * 8 + (lane & 3) * 2;
                float as0 = __ldg(&attsrc[col]), as1 = __ldg(&attsrc[col + 1]);
                float ad0 = __ldg(&attdst[col]), ad1 = __ldg(&attdst[col + 1]);
                float2 v0 = make_float2(acc[t][0], acc[t][1]);
                float2 v1 = make_float2(acc[t][2], acc[t][3]);
                sd[mi][0] += v0.x * as0 + v0.y * as1;
                dd[mi][0] += v0.x * ad0 + v0.y * ad1;
                sd[mi][1] += v1.x * as0 + v1.y * as1;
                dd[mi][1] += v1.x * ad0 + v1.y * ad1;
                if (rlo < N_NODES) {
                    __half2 p = __float22half2_rn(v0);
                    *(uint32_t*)&g_xh[(size_t)rlo * HID + col] = *(uint32_t*)&p;
                }
                if (rhi < N_NODES) {
                    __half2 p = __float22half2_rn(v1);
                    *(uint32_t*)&g_xh[(size_t)rhi * HID + col] = *(uint32_t*)&p;
                }
            }
        }
    }
#pragma unroll
    for (int o = 1; o <= 2; o <<= 1) {
#pragma unroll
        for (int mi = 0; mi < 2; mi++)
#pragma unroll
            for (int hh = 0; hh < 2; hh++) {
                sd[mi][hh] += __shfl_xor_sync(0xffffffffu, sd[mi][hh], o);
                dd[mi][hh] += __shfl_xor_sync(0xffffffffu, dd[mi][hh], o);
            }
    }
    float* sdp = (float*)sm;
    float* ddp = sdp + 256;
    if ((lane & 3) == 0) {
#pragma unroll
        for (int mi = 0; mi < 2; mi++)
#pragma unroll
            for (int hh = 0; hh < 2; hh++) {
                int rt = warp_m * 32 + mi * 16 + (lane >> 2) + hh * 8;
                sdp[rt * 2 + warp_n] = sd[mi][hh];
                ddp[rt * 2 + warp_n] = dd[mi][hh];
            }
    }
    __syncthreads();
    if (tid < 128) {
        int gr = row0 + tid;
        if (gr < N_NODES) {
            g_asrc[gr] = sdp[tid * 2] + sdp[tid * 2 + 1];
            g_adst[gr] = ddp[tid * 2] + ddp[tid * 2 + 1];
        }
    }
}

// ---------------- histogram (real edges only; self-loops analytic) ----------------
__global__ void hist_kernel(const void* __restrict__ adj) {
    int i = blockIdx.x * blockDim.x + threadIdx.x;
    if (i >= N_EDGES) return;
    int is64 = g_is64;
    int d = load_adj(adj, (long long)N_EDGES + i, is64);
    atomicAdd(&g_deg[d], 1);
}

// ---------------- scan: per-block sums, then fused base+scan ----------------
__global__ void __launch_bounds__(1024) scan1_kernel() {
    __shared__ int ws[32];
    int tid = threadIdx.x, lane = tid & 31, wid = tid >> 5;
    int i = blockIdx.x * 1024 + tid;
    int v = (i < N_NODES) ? g_deg[i] : 0;
#pragma unroll
    for (int o = 16; o; o >>= 1) v += __shfl_down_sync(0xffffffffu, v, o);
    if (lane == 0) ws[wid] = v;
    __syncthreads();
    if (wid == 0) {
        int s = ws[lane];
#pragma unroll
        for (int o = 16; o; o >>= 1) s += __shfl_down_sync(0xffffffffu, s, o);
        if (lane == 0) g_part[blockIdx.x] = s;
    }
}
__global__ void __launch_bounds__(1024) scan2_kernel() {
    __shared__ int ws[32];
    __shared__ int s_base;
    int tid = threadIdx.x, lane = tid & 31, wid = tid >> 5;
    {
        int p = (tid < blockIdx.x) ? g_part[tid] : 0;
#pragma unroll
        for (int o = 16; o; o >>= 1) p += __shfl_down_sync(0xffffffffu, p, o);
        if (lane == 0) ws[wid] = p;
        __syncthreads();
        if (wid == 0) {
            int s = ws[lane];
#pragma unroll
            for (int o = 16; o; o >>= 1) s += __shfl_down_sync(0xffffffffu, s, o);
            if (lane == 0) s_base = s;
        }
        __syncthreads();
    }
    int i = blockIdx.x * 1024 + tid;
    int v = (i < N_NODES) ? g_deg[i] : 0;
    int incl = v;
#pragma unroll
    for (int o = 1; o < 32; o <<= 1) {
        int t = __shfl_up_sync(0xffffffffu, incl, o);
        if (lane >= o) incl += t;
    }
    __syncthreads();
    if (lane == 31) ws[wid] = incl;
    __syncthreads();
    if (wid == 0) {
        int s = ws[lane];
        int sc = s;
#pragma unroll
        for (int o = 1; o < 32; o <<= 1) {
            int t = __shfl_up_sync(0xffffffffu, sc, o);
            if (lane >= o) sc += t;
        }
        ws[lane] = sc - s;
    }
    __syncthreads();
    int excl = s_base + ws[wid] + incl - v;
    if (i < N_NODES) {
        g_off[i] = excl;
        g_cur[i] = excl;
        if (i == N_NODES - 1) g_off[N_NODES] = excl + v;
    }
}

// ---------------- scatter src ids only (no GEMM dependency!) ----------------
__global__ void scatter_src_kernel(const void* __restrict__ adj) {
    int i = blockIdx.x * blockDim.x + threadIdx.x;
    if (i >= N_EDGES) return;
    int is64 = g_is64;
    int s = load_adj(adj, i, is64);
    int d = load_adj(adj, (long long)N_EDGES + i, is64);
    int pos = atomicAdd(&g_cur[d], 1);
    g_src[pos] = s;
}

// ---------------- aggregation: on-the-fly softmax (dst logit is warp-local) ----------------
__global__ void agg_kernel(const float* __restrict__ bias, float* __restrict__ out) {
    int w = (blockIdx.x * blockDim.x + threadIdx.x) >> 5;
    int lane = threadIdx.x & 31;
    if (w >= N_NODES) return;
    int st = g_off[w], en = g_off[w + 1];
    const float adst_w = g_adst[w];
    // self-loop term
    float es = g_asrc[w] + adst_w;
    es = (es > 0.f) ? es : 0.2f * es;
    float ssum = __expf(es);
    float4 acc;
    {
        uint2 raw = *(const uint2*)&g_xh[(size_t)w * HID + lane * 4];
        float2 f0 = __half22float2(*reinterpret_cast<__half2*>(&raw.x));
        float2 f1 = __half22float2(*reinterpret_cast<__half2*>(&raw.y));
        acc = make_float4(ssum * f0.x, ssum * f0.y, ssum * f1.x, ssum * f1.y);
    }
    for (int j = st; j < en; j++) {
        int s = g_src[j];                          // broadcast load
        float e = g_asrc[s] + adst_w;              // broadcast load
        e = (e > 0.f) ? e : 0.2f * e;
        float ex = __expf(e);
        uint2 raw = *(const uint2*)&g_xh[(size_t)s * HID + lane * 4];
        float2 f0 = __half22float2(*reinterpret_cast<__half2*>(&raw.x));
        float2 f1 = __half22float2(*reinterpret_cast<__half2*>(&raw.y));
        ssum += ex;
        acc.x += ex * f0.x;
        acc.y += ex * f0.y;
        acc.z += ex * f1.x;
        acc.w += ex * f1.y;
    }
    float inv = 1.f / (ssum + 1e-16f);
    float4 b = *(const float4*)&bias[lane * 4];
    float4 o;
    o.x = acc.x * inv + b.x;
    o.y = acc.y * inv + b.y;
    o.z = acc.z * inv + b.z;
    o.w = acc.w * inv + b.w;
    o.x = (o.x > 0.f) ? o.x : 0.25f * o.x;
    o.y = (o.y > 0.f) ? o.y : 0.25f * o.y;
    o.z = (o.z > 0.f) ? o.z : 0.25f * o.z;
    o.w = (o.w > 0.f) ? o.w : 0.25f * o.w;
    *(float4*)&out[(size_t)w * HID + lane * 4] = o;
}

// ---------------- launcher: full edge pipeline forked parallel to GEMM ----------------
extern "C" void kernel_launch(void* const* d_in, const int* in_sizes, int n_in,
                              void* d_out, int out_size) {
    const float* data   = (const float*)d_in[0];
    const void*  adj    = (const void*)d_in[1];
    const float* W      = (const float*)d_in[2];
    const float* attsrc = (const float*)d_in[3];
    const float* attdst = (const float*)d_in[4];
    const float* bias   = (const float*)d_in[5];
    float* out = (float*)d_out;

    cudaFuncSetAttribute(gemm_kernel, cudaFuncAttributeMaxDynamicSharedMemorySize, S_BYTES);

    // fork/join resources; created per call, intentionally not destroyed
    // (kernel_launch runs ~2x total; replays use the captured graph only).
    cudaStream_t s2;
    cudaStreamCreateWithFlags(&s2, cudaStreamNonBlocking);
    cudaEvent_t ev_fork, ev_join;
    cudaEventCreateWithFlags(&ev_fork, cudaEventDisableTiming);
    cudaEventCreateWithFlags(&ev_join, cudaEventDisableTiming);

    prep_kernel<<<(N_NODES + 255) / 256, 256>>>(adj, W);

    // fork: hist -> scan -> scatter_src (no GEMM dependency anywhere)
    cudaEventRecord(ev_fork, 0);
    cudaStreamWaitEvent(s2, ev_fork, 0);
    hist_kernel<<<(N_EDGES + 255) / 256, 256, 0, s2>>>(adj);
    scan1_kernel<<<NBLK_SCAN, 1024, 0, s2>>>();
    scan2_kernel<<<NBLK_SCAN, 1024, 0, s2>>>();
    scatter_src_kernel<<<(N_EDGES + 255) / 256, 256, 0, s2>>>(adj);
    cudaEventRecord(ev_join, s2);

    // main stream: GEMM runs concurrently with the whole edge pipeline
    gemm_kernel<<<(N_NODES + TILE_M - 1) / TILE_M, 256, S_BYTES>>>(data, attsrc, attdst);

    // join: agg needs gemm (asrc/adst/xh) + fork (offsets, sorted srcs)
    cudaStreamWaitEvent(0, ev_join, 0);
    agg_kernel<<<(N_NODES * 32 + 255) / 256, 256>>>(bias, out);
}